// round 4
// baseline (speedup 1.0000x reference)
#include <cuda_runtime.h>

#define B_   2048
#define T_   128
#define S_   256
#define H_   64
#define E_   32
#define V_   29
#define G4   256   // 4*H
#define ES   68    // enc SMEM row stride (floats); cols [0:32) at +0, [32:64) at +34

typedef unsigned long long ull;

struct __align__(16) Smem {
    float enc[S_ * ES];        // 69632 B  (P3 column access only)
    float gate_emb[V_ * G4];   // 29696 B  precomputed W_ih[:, :32]@emb[v] + bias
    float fcW[V_ * 128 + 32];  // 14976 B
    float embS[V_ * E_];       //  3712 B  (prologue only)
    float part[16 * 64];       //  4096 B  context partials [q][hd]
    float scores[S_];          //  e_s (no max subtraction; |score| bounded)
    float gates[G4];
    float bias[G4];            //  prologue only (folded into gate_emb)
    float comb[128];           //  [0:64)=h  [64:128)=ctx
    float fcb[32];
    float redsum[16];
    int   ytok[T_];
};

__device__ __forceinline__ ull pack2(float lo, float hi) {
    ull r; asm("mov.b64 %0, {%1, %2};" : "=l"(r) : "f"(lo), "f"(hi)); return r;
}
__device__ __forceinline__ ull fma2(ull a, ull b, ull c) {
    ull d; asm("fma.rn.f32x2 %0, %1, %2, %3;" : "=l"(d) : "l"(a), "l"(b), "l"(c));
    return d;
}
__device__ __forceinline__ float2 unpack2(ull v) {
    float lo, hi; asm("mov.b64 {%0, %1}, %2;" : "=f"(lo), "=f"(hi) : "l"(v));
    return make_float2(lo, hi);
}
__device__ __forceinline__ float sigmoid_(float z) {
    return 1.0f / (1.0f + __expf(-z));
}
__device__ __forceinline__ float tanh_(float x) {
    return 1.0f - 2.0f / (__expf(2.0f * x) + 1.0f);
}

extern "C" __global__ void __launch_bounds__(512, 1)
decoder_persist_kernel(const int* __restrict__ y,
                       const float* __restrict__ h0,
                       const float* __restrict__ c0,
                       const float* __restrict__ enc_g,
                       const float* __restrict__ embt,
                       const float* __restrict__ Wih,
                       const float* __restrict__ Whh,
                       const float* __restrict__ bih,
                       const float* __restrict__ bhh,
                       const float* __restrict__ fcWg,
                       const float* __restrict__ fcbg,
                       float* __restrict__ out)
{
    extern __shared__ __align__(16) char smem_raw[];
    Smem& sm = *reinterpret_cast<Smem*>(smem_raw);
    const int tid  = threadIdx.x;
    const int b    = blockIdx.x;
    const int lane = tid & 31;
    const int wrp  = tid >> 5;
    const int r    = tid >> 1;   // row id for P1 scores and P4 gates
    const int half = tid & 1;

    // ---- persistent registers: enc row-half, W_ih ctx-part, W_hh half ----
    ull enc2[16], wihc2[16], whh2[16];
    {
        const float4* ep = reinterpret_cast<const float4*>(
            enc_g + (size_t)b * (S_ * H_) + r * H_ + 32 * half);
        #pragma unroll
        for (int k = 0; k < 8; k++) {
            float4 v = ep[k];
            enc2[2*k] = pack2(v.x, v.y); enc2[2*k+1] = pack2(v.z, v.w);
        }
        const float4* wi = reinterpret_cast<const float4*>(Wih + r * 96 + 32 + 32 * half);
        #pragma unroll
        for (int k = 0; k < 8; k++) {
            float4 v = wi[k];
            wihc2[2*k] = pack2(v.x, v.y); wihc2[2*k+1] = pack2(v.z, v.w);
        }
        const float4* wh = reinterpret_cast<const float4*>(Whh + r * 64 + 32 * half);
        #pragma unroll
        for (int k = 0; k < 8; k++) {
            float4 v = wh[k];
            whh2[2*k] = pack2(v.x, v.y); whh2[2*k+1] = pack2(v.z, v.w);
        }
    }

    // ---- stage enc SMEM (mid-row pad layout), constants ----
    {
        const float2* eb = reinterpret_cast<const float2*>(enc_g + (size_t)b * (S_ * H_));
        for (int i2 = tid; i2 < (S_ * H_) / 2; i2 += 512) {
            float2 v = eb[i2];
            int s  = i2 >> 5;
            int h2 = (i2 & 31) << 1;
            int dst = s * ES + h2 + ((h2 >= 32) ? 2 : 0);
            *reinterpret_cast<float2*>(&sm.enc[dst]) = v;
        }
    }
    for (int i = tid; i < V_ * 128; i += 512) sm.fcW[i] = fcWg[i];
    for (int i = tid; i < V_ * E_;  i += 512) sm.embS[i] = embt[i];
    if (tid < G4) sm.bias[tid] = bih[tid] + bhh[tid];
    if (tid < V_) sm.fcb[tid]  = fcbg[tid];
    if (tid < T_) sm.ytok[tid] = y[b * T_ + tid];
    float creg = 0.0f;
    if (tid < H_) {
        sm.comb[tid] = h0[b * H_ + tid];
        creg = c0[b * H_ + tid];
    }
    __syncthreads();

    // ---- prologue: gate_emb[v][r] = W_ih[r, :32] . emb[v] + bias[r] ----
    {
        float4 we[4];
        const float4* wg = reinterpret_cast<const float4*>(Wih + r * 96 + 16 * half);
        #pragma unroll
        for (int k = 0; k < 4; k++) we[k] = wg[k];
        float brow = sm.bias[r];
        for (int v = 0; v < V_; v++) {
            const float4* em = reinterpret_cast<const float4*>(sm.embS + v * E_ + 16 * half);
            float a = 0.f;
            #pragma unroll
            for (int k = 0; k < 4; k++) {
                float4 e = em[k];
                a += we[k].x*e.x + we[k].y*e.y + we[k].z*e.z + we[k].w*e.w;
            }
            a += __shfl_xor_sync(0xffffffffu, a, 1);
            if (half == 0) sm.gate_emb[v * G4 + r] = a + brow;
        }
    }
    __syncthreads();

    float* outp = out + (size_t)b * T_ * V_;

    for (int t = 0; t < T_; t++) {
        // ---- P1: e_s = exp(enc[s,:].h)  — enc from registers, h broadcast ----
        {
            const float4* hp = reinterpret_cast<const float4*>(sm.comb + 32 * half);
            ull a0 = 0ull, a1 = 0ull;
            #pragma unroll
            for (int k = 0; k < 8; k++) {
                float4 hv = hp[k];
                a0 = fma2(enc2[2*k],   pack2(hv.x, hv.y), a0);
                a1 = fma2(enc2[2*k+1], pack2(hv.z, hv.w), a1);
            }
            float2 fa = unpack2(a0), fb = unpack2(a1);
            float sc = (fa.x + fa.y) + (fb.x + fb.y);
            sc += __shfl_xor_sync(0xffffffffu, sc, 1);
            float e = __expf(sc);
            if (half == 0) sm.scores[r] = e;
            float su = e;
            #pragma unroll
            for (int o = 16; o > 1; o >>= 1)
                su += __shfl_xor_sync(0xffffffffu, su, o);
            // lane 0 = sum over even lanes = warp's 16 distinct scores, once each
            if (lane == 0) sm.redsum[wrp] = su;
        }
        __syncthreads();  // bar1: scores, redsum

        // ---- P3: context partials (warp q handles 16 s-rows) ----
        {
            const int sbase = wrp * 16;
            const float*  ebase = sm.enc + sbase * ES + 2 * lane + ((lane >> 4) & 1) * 2;
            const float4* sp = reinterpret_cast<const float4*>(sm.scores + sbase);
            float ax = 0.f, ay = 0.f;
            #pragma unroll
            for (int c = 0; c < 4; c++) {
                float4 sv = sp[c];
                float2 e0 = *reinterpret_cast<const float2*>(ebase + (4*c + 0) * ES);
                float2 e1 = *reinterpret_cast<const float2*>(ebase + (4*c + 1) * ES);
                float2 e2 = *reinterpret_cast<const float2*>(ebase + (4*c + 2) * ES);
                float2 e3 = *reinterpret_cast<const float2*>(ebase + (4*c + 3) * ES);
                ax += sv.x * e0.x; ay += sv.x * e0.y;
                ax += sv.y * e1.x; ay += sv.y * e1.y;
                ax += sv.z * e2.x; ay += sv.z * e2.y;
                ax += sv.w * e3.x; ay += sv.w * e3.y;
            }
            *reinterpret_cast<float2*>(&sm.part[wrp * 64 + 2 * lane]) = make_float2(ax, ay);
        }
        __syncthreads();  // bar2: part

        // ---- ctx reduce + normalize -> comb[64:128) ----
        if (tid < H_) {
            float ssum = 0.f;
            #pragma unroll
            for (int k = 0; k < 16; k++) ssum += sm.redsum[k];
            float inv = 1.0f / ssum;
            float ctx = 0.f;
            #pragma unroll
            for (int q = 0; q < 16; q++) ctx += sm.part[q * 64 + tid];
            sm.comb[H_ + tid] = ctx * inv;
        }
        __syncthreads();  // bar3: comb[64:]

        // ---- P4: gates = gate_emb[tok] + W_ih_ctx@ctx + W_hh@h ----
        {
            const float4* xp = reinterpret_cast<const float4*>(sm.comb + 64 + 32 * half);
            const float4* hp = reinterpret_cast<const float4*>(sm.comb + 32 * half);
            ull a0 = 0ull, a1 = 0ull;
            #pragma unroll
            for (int k = 0; k < 8; k++) {
                float4 xv = xp[k];
                a0 = fma2(wihc2[2*k],   pack2(xv.x, xv.y), a0);
                a1 = fma2(wihc2[2*k+1], pack2(xv.z, xv.w), a1);
            }
            #pragma unroll
            for (int k = 0; k < 8; k++) {
                float4 hv = hp[k];
                a0 = fma2(whh2[2*k],   pack2(hv.x, hv.y), a0);
                a1 = fma2(whh2[2*k+1], pack2(hv.z, hv.w), a1);
            }
            float2 fa = unpack2(a0), fb = unpack2(a1);
            float g = (fa.x + fa.y) + (fb.x + fb.y);
            g += __shfl_xor_sync(0xffffffffu, g, 1);
            if (half == 0)
                sm.gates[r] = g + sm.gate_emb[sm.ytok[t] * G4 + r];
        }
        __syncthreads();  // bar4: gates

        // ---- P5: LSTM cell -> comb[0:64) ----
        if (tid < H_) {
            float ig = sm.gates[tid];
            float fg = sm.gates[H_ + tid];
            float gg = sm.gates[2 * H_ + tid];
            float og = sm.gates[3 * H_ + tid];
            creg = sigmoid_(fg) * creg + sigmoid_(ig) * tanh_(gg);
            sm.comb[tid] = sigmoid_(og) * tanh_(creg);
        }
        __syncthreads();  // bar5: h

        // ---- P6: logits (16 threads per vocab row) ----
        {
            int v = tid >> 4, p = tid & 15;
            float acc = 0.0f;
            if (v < V_) {
                const float4* fw = reinterpret_cast<const float4*>(sm.fcW + v * 128 + p * 8);
                const float4* cb = reinterpret_cast<const float4*>(sm.comb + p * 8);
                float4 w0 = fw[0], w1 = fw[1];
                float4 c0v = cb[0], c1v = cb[1];
                acc = w0.x*c0v.x + w0.y*c0v.y + w0.z*c0v.z + w0.w*c0v.w
                    + w1.x*c1v.x + w1.y*c1v.y + w1.z*c1v.z + w1.w*c1v.w;
            }
            #pragma unroll
            for (int o = 8; o; o >>= 1)
                acc += __shfl_xor_sync(0xffffffffu, acc, o);
            if (p == 0 && v < V_)
                outp[t * V_ + v] = acc + sm.fcb[v];
        }
        // no trailing barrier: next-step writes to comb occur only after
        // bar2/bar4 of step t+1, which transitively require all warps to
        // have finished P6 of step t.
    }
}

extern "C" void kernel_launch(void* const* d_in, const int* in_sizes, int n_in,
                              void* d_out, int out_size) {
    const int*   y    = (const int*)d_in[0];
    const float* h0   = (const float*)d_in[1];
    const float* c0   = (const float*)d_in[2];
    const float* enc  = (const float*)d_in[3];
    const float* emb  = (const float*)d_in[4];
    const float* Wih  = (const float*)d_in[5];
    const float* Whh  = (const float*)d_in[6];
    const float* bih  = (const float*)d_in[7];
    const float* bhh  = (const float*)d_in[8];
    const float* fcW  = (const float*)d_in[9];
    const float* fcb  = (const float*)d_in[10];
    float* out = (float*)d_out;

    size_t smem = sizeof(Smem);
    cudaFuncSetAttribute(decoder_persist_kernel,
                         cudaFuncAttributeMaxDynamicSharedMemorySize, (int)smem);
    decoder_persist_kernel<<<B_, 512, smem>>>(y, h0, c0, enc, emb,
                                              Wih, Whh, bih, bhh, fcW, fcb, out);
}